// round 1
// baseline (speedup 1.0000x reference)
#include <cuda_runtime.h>
#include <math.h>

#define N_NODES  100000
#define N_EDGES  3200000
#define N_GRAPHS 512

// ---------------- scratch (static device globals; no allocation) ----------------
__device__ float g_bufA[(size_t)N_NODES * 256];
__device__ float g_bufB[(size_t)N_NODES * 256];
__device__ int   g_deg[N_NODES];
__device__ float g_dinv[N_NODES];
__device__ int   g_rowptr[N_NODES + 1];
__device__ int   g_cursor[N_NODES];
__device__ int   g_col[N_EDGES];
__device__ float g_pool[N_GRAPHS * 64];
__device__ int   g_cnt[N_GRAPHS];

// ---------------- init ----------------
__global__ void k_init() {
    int i = blockIdx.x * blockDim.x + threadIdx.x;
    if (i < N_NODES) g_deg[i] = 1;               // self loop
    if (i < N_GRAPHS * 64) g_pool[i] = 0.f;
    if (i < N_GRAPHS) g_cnt[i] = 0;
}

// ---------------- degree histogram over dst ----------------
__global__ void k_hist(const int* __restrict__ dst) {
    int i = blockIdx.x * blockDim.x + threadIdx.x;
    if (i < N_EDGES) atomicAdd(&g_deg[dst[i]], 1);
}

__global__ void k_dinv() {
    int i = blockIdx.x * blockDim.x + threadIdx.x;
    if (i < N_NODES) g_dinv[i] = rsqrtf((float)g_deg[i]);
}

// ---------------- single-block exclusive scan of (deg-1) -> rowptr ----------------
__global__ void k_scan() {
    __shared__ int s[1024];
    __shared__ int carry_s;
    int t = threadIdx.x;
    if (t == 0) carry_s = 0;
    __syncthreads();
    for (int base = 0; base < N_NODES; base += 1024) {
        int i = base + t;
        int v = (i < N_NODES) ? (g_deg[i] - 1) : 0;
        s[t] = v;
        __syncthreads();
        for (int off = 1; off < 1024; off <<= 1) {
            int y = 0;
            if (t >= off) y = s[t - off];
            __syncthreads();
            s[t] += y;
            __syncthreads();
        }
        int incl = s[t];
        int carry = carry_s;
        if (i < N_NODES) g_rowptr[i] = carry + incl - v;
        __syncthreads();
        if (t == 1023) carry_s = carry + s[1023];
        __syncthreads();
    }
    if (t == 0) g_rowptr[N_NODES] = carry_s;
}

__global__ void k_cursor() {
    int i = blockIdx.x * blockDim.x + threadIdx.x;
    if (i < N_NODES) g_cursor[i] = g_rowptr[i];
}

__global__ void k_fill(const int* __restrict__ src, const int* __restrict__ dst) {
    int i = blockIdx.x * blockDim.x + threadIdx.x;
    if (i < N_EDGES) {
        int d = dst[i];
        int p = atomicAdd(&g_cursor[d], 1);
        g_col[p] = src[i];
    }
}

// ---------------- tiled fp32 GEMM: Out[N,Cn] = A[N,K] @ W[K,Cn] (+bias, relu) ----------------
__global__ void k_gemm(const float* __restrict__ A, const float* __restrict__ W,
                       float* __restrict__ Out, int K, int Cn,
                       const float* __restrict__ bias, int relu) {
    const int BM = 64, BN = 64, BK = 16;
    __shared__ float As[BK][BM + 4];
    __shared__ float Ws[BK][BN + 4];
    int tid = threadIdx.x;                 // 256 threads
    int tx = tid & 15, ty = tid >> 4;
    int row0 = blockIdx.y * BM, col0 = blockIdx.x * BN;
    int ar = tid >> 2, aq = tid & 3;       // A loader: row ar, float4 #aq
    int wr = tid >> 4, wq = tid & 15;      // W loader: k-row wr, float4 #wq

    float acc[4][4];
#pragma unroll
    for (int i = 0; i < 4; i++)
#pragma unroll
        for (int j = 0; j < 4; j++) acc[i][j] = 0.f;

    int arow = row0 + ar;
    bool avalid = arow < N_NODES;
    const float* Aptr = A + (size_t)(avalid ? arow : 0) * K + aq * 4;

    for (int kk = 0; kk < K; kk += BK) {
        float4 av = make_float4(0.f, 0.f, 0.f, 0.f);
        if (avalid) av = *(const float4*)(Aptr + kk);
        As[aq * 4 + 0][ar] = av.x;
        As[aq * 4 + 1][ar] = av.y;
        As[aq * 4 + 2][ar] = av.z;
        As[aq * 4 + 3][ar] = av.w;
        float4 wv = *(const float4*)(W + (size_t)(kk + wr) * Cn + col0 + wq * 4);
        *(float4*)&Ws[wr][wq * 4] = wv;
        __syncthreads();
#pragma unroll
        for (int k = 0; k < BK; k++) {
            float4 a = *(const float4*)&As[k][ty * 4];
            float4 b = *(const float4*)&Ws[k][tx * 4];
            acc[0][0] += a.x * b.x; acc[0][1] += a.x * b.y; acc[0][2] += a.x * b.z; acc[0][3] += a.x * b.w;
            acc[1][0] += a.y * b.x; acc[1][1] += a.y * b.y; acc[1][2] += a.y * b.z; acc[1][3] += a.y * b.w;
            acc[2][0] += a.z * b.x; acc[2][1] += a.z * b.y; acc[2][2] += a.z * b.z; acc[2][3] += a.z * b.w;
            acc[3][0] += a.w * b.x; acc[3][1] += a.w * b.y; acc[3][2] += a.w * b.z; acc[3][3] += a.w * b.w;
        }
        __syncthreads();
    }

    float4 bb = make_float4(0.f, 0.f, 0.f, 0.f);
    if (bias) bb = *(const float4*)(bias + col0 + tx * 4);
#pragma unroll
    for (int i = 0; i < 4; i++) {
        int r = row0 + ty * 4 + i;
        if (r < N_NODES) {
            float4 o;
            o.x = acc[i][0] + bb.x; o.y = acc[i][1] + bb.y;
            o.z = acc[i][2] + bb.z; o.w = acc[i][3] + bb.w;
            if (relu) {
                o.x = fmaxf(o.x, 0.f); o.y = fmaxf(o.y, 0.f);
                o.z = fmaxf(o.z, 0.f); o.w = fmaxf(o.w, 0.f);
            }
            *(float4*)(Out + (size_t)r * Cn + col0 + tx * 4) = o;
        }
    }
}

// ---------------- CSR aggregation: O[n] = dinv[n]*(sum_e dinv[src]*T[src] + dinv[n]*T[n]) + b ----------------
// one warp per node; 8 nodes per 256-thread block
template <int C>
__global__ void k_agg(const float* __restrict__ T, float* __restrict__ O,
                      const float* __restrict__ bias, int relu) {
    int warp = threadIdx.x >> 5;
    int lane = threadIdx.x & 31;
    int n = blockIdx.x * 8 + warp;
    float dn = g_dinv[n];
    int s = g_rowptr[n], e = g_rowptr[n + 1];

    if (C == 256) {
        int o0 = lane * 4, o1 = 128 + lane * 4;
        float4 a0 = *(const float4*)(T + (size_t)n * C + o0);
        float4 a1 = *(const float4*)(T + (size_t)n * C + o1);
        a0.x *= dn; a0.y *= dn; a0.z *= dn; a0.w *= dn;
        a1.x *= dn; a1.y *= dn; a1.z *= dn; a1.w *= dn;
        for (int j = s; j < e; j++) {
            int u = g_col[j];
            float w = g_dinv[u];
            const float* r = T + (size_t)u * C;
            float4 v0 = *(const float4*)(r + o0);
            float4 v1 = *(const float4*)(r + o1);
            a0.x += w * v0.x; a0.y += w * v0.y; a0.z += w * v0.z; a0.w += w * v0.w;
            a1.x += w * v1.x; a1.y += w * v1.y; a1.z += w * v1.z; a1.w += w * v1.w;
        }
        float4 b0 = make_float4(0.f, 0.f, 0.f, 0.f), b1 = b0;
        if (bias) { b0 = *(const float4*)(bias + o0); b1 = *(const float4*)(bias + o1); }
        float4 r0, r1;
        r0.x = dn * a0.x + b0.x; r0.y = dn * a0.y + b0.y; r0.z = dn * a0.z + b0.z; r0.w = dn * a0.w + b0.w;
        r1.x = dn * a1.x + b1.x; r1.y = dn * a1.y + b1.y; r1.z = dn * a1.z + b1.z; r1.w = dn * a1.w + b1.w;
        if (relu) {
            r0.x = fmaxf(r0.x, 0.f); r0.y = fmaxf(r0.y, 0.f); r0.z = fmaxf(r0.z, 0.f); r0.w = fmaxf(r0.w, 0.f);
            r1.x = fmaxf(r1.x, 0.f); r1.y = fmaxf(r1.y, 0.f); r1.z = fmaxf(r1.z, 0.f); r1.w = fmaxf(r1.w, 0.f);
        }
        *(float4*)(O + (size_t)n * C + o0) = r0;
        *(float4*)(O + (size_t)n * C + o1) = r1;
    } else if (C == 128) {
        int o0 = lane * 4;
        float4 a0 = *(const float4*)(T + (size_t)n * C + o0);
        a0.x *= dn; a0.y *= dn; a0.z *= dn; a0.w *= dn;
        for (int j = s; j < e; j++) {
            int u = g_col[j];
            float w = g_dinv[u];
            float4 v0 = *(const float4*)(T + (size_t)u * C + o0);
            a0.x += w * v0.x; a0.y += w * v0.y; a0.z += w * v0.z; a0.w += w * v0.w;
        }
        float4 b0 = make_float4(0.f, 0.f, 0.f, 0.f);
        if (bias) b0 = *(const float4*)(bias + o0);
        float4 r0;
        r0.x = dn * a0.x + b0.x; r0.y = dn * a0.y + b0.y; r0.z = dn * a0.z + b0.z; r0.w = dn * a0.w + b0.w;
        if (relu) {
            r0.x = fmaxf(r0.x, 0.f); r0.y = fmaxf(r0.y, 0.f); r0.z = fmaxf(r0.z, 0.f); r0.w = fmaxf(r0.w, 0.f);
        }
        *(float4*)(O + (size_t)n * C + o0) = r0;
    } else { // C == 64
        int o0 = lane * 2;
        float2 a0 = *(const float2*)(T + (size_t)n * C + o0);
        a0.x *= dn; a0.y *= dn;
        for (int j = s; j < e; j++) {
            int u = g_col[j];
            float w = g_dinv[u];
            float2 v0 = *(const float2*)(T + (size_t)u * C + o0);
            a0.x += w * v0.x; a0.y += w * v0.y;
        }
        float2 b0 = make_float2(0.f, 0.f);
        if (bias) b0 = *(const float2*)(bias + o0);
        float rx = dn * a0.x + b0.x, ry = dn * a0.y + b0.y;
        if (relu) { rx = fmaxf(rx, 0.f); ry = fmaxf(ry, 0.f); }
        *(float2*)(O + (size_t)n * C + o0) = make_float2(rx, ry);
    }
}

// ---------------- pooling ----------------
__global__ void k_pool(const float* __restrict__ h, const int* __restrict__ batch) {
    int idx = blockIdx.x * blockDim.x + threadIdx.x;
    if (idx >= N_NODES * 16) return;
    int n = idx >> 4, q = idx & 15;
    int g = batch[n];
    float4 v = *(const float4*)(h + (size_t)n * 64 + q * 4);
    float* p = g_pool + g * 64 + q * 4;
    atomicAdd(p + 0, v.x);
    atomicAdd(p + 1, v.y);
    atomicAdd(p + 2, v.z);
    atomicAdd(p + 3, v.w);
}

__global__ void k_cnt(const int* __restrict__ batch) {
    int i = blockIdx.x * blockDim.x + threadIdx.x;
    if (i < N_NODES) atomicAdd(&g_cnt[batch[i]], 1);
}

// ---------------- head: mean, linear, log_softmax + softmax ----------------
__global__ void k_final(const float* __restrict__ Wlin, const float* __restrict__ blin,
                        float* __restrict__ out) {
    int g = blockIdx.x;
    int t = threadIdx.x;  // 64 threads
    __shared__ float mean[64];
    __shared__ float logits[10];
    __shared__ float red2[2];
    float c = (float)g_cnt[g];
    float inv = 1.0f / fmaxf(c, 1.0f);
    mean[t] = g_pool[g * 64 + t] * inv;
    __syncthreads();
    if (t < 10) {
        float s = blin[t];
        for (int k = 0; k < 64; k++) s += mean[k] * Wlin[k * 10 + t];
        logits[t] = s;
    }
    __syncthreads();
    if (t == 0) {
        float mx = logits[0];
        for (int l = 1; l < 10; l++) mx = fmaxf(mx, logits[l]);
        float se = 0.f;
        for (int l = 0; l < 10; l++) se += expf(logits[l] - mx);
        red2[0] = mx;
        red2[1] = se;
    }
    __syncthreads();
    if (t < 10) {
        float lsm = logits[t] - red2[0] - logf(red2[1]);
        out[g * 10 + t] = lsm;                       // log_softmax
        out[N_GRAPHS * 10 + g * 10 + t] = expf(lsm); // softmax
    }
}

// ---------------- launch ----------------
extern "C" void kernel_launch(void* const* d_in, const int* in_sizes, int n_in,
                              void* d_out, int out_size) {
    const float* x     = (const float*)d_in[0];
    const int*   ei    = (const int*)d_in[1];
    const int*   batch = (const int*)d_in[2];
    const float* W1 = (const float*)d_in[4];  const float* b1 = (const float*)d_in[5];
    const float* W2 = (const float*)d_in[6];  const float* b2 = (const float*)d_in[7];
    const float* W3 = (const float*)d_in[8];  const float* b3 = (const float*)d_in[9];
    const float* W4 = (const float*)d_in[10]; const float* b4 = (const float*)d_in[11];
    const float* W5 = (const float*)d_in[12]; const float* b5 = (const float*)d_in[13];
    const float* W6 = (const float*)d_in[14]; const float* b6 = (const float*)d_in[15];
    const float* Wlin = (const float*)d_in[16];
    const float* blin = (const float*)d_in[17];
    const int* src = ei;
    const int* dst = ei + N_EDGES;
    float* out = (float*)d_out;

    float *bufA, *bufB;
    cudaGetSymbolAddress((void**)&bufA, g_bufA);
    cudaGetSymbolAddress((void**)&bufB, g_bufB);

    const int TB = 256;
    int gN = (N_NODES + TB - 1) / TB;
    int gE = (N_EDGES + TB - 1) / TB;

    // preprocessing
    k_init<<<gN, TB>>>();
    k_hist<<<gE, TB>>>(dst);
    k_dinv<<<gN, TB>>>();
    k_scan<<<1, 1024>>>();
    k_cursor<<<gN, TB>>>();
    k_fill<<<gE, TB>>>(src, dst);

    int aggBlocks = N_NODES / 8;
    dim3 g256(256 / 64, (N_NODES + 63) / 64);
    dim3 g128(128 / 64, (N_NODES + 63) / 64);
    dim3 g64(64 / 64, (N_NODES + 63) / 64);

    // L1: aggregate-first (128-wide edges), then GEMM 128->256 with bias+relu
    k_agg<128><<<aggBlocks, 256>>>(x, bufA, nullptr, 0);
    k_gemm<<<g256, 256>>>(bufA, W1, bufB, 128, 256, b1, 1);
    // L2: transform-first
    k_gemm<<<g256, 256>>>(bufB, W2, bufA, 256, 256, nullptr, 0);
    k_agg<256><<<aggBlocks, 256>>>(bufA, bufB, b2, 1);
    // L3
    k_gemm<<<g256, 256>>>(bufB, W3, bufA, 256, 256, nullptr, 0);
    k_agg<256><<<aggBlocks, 256>>>(bufA, bufB, b3, 1);
    // L4: 256->128, transform-first (128-wide edges)
    k_gemm<<<g128, 256>>>(bufB, W4, bufA, 256, 128, nullptr, 0);
    k_agg<128><<<aggBlocks, 256>>>(bufA, bufB, b4, 1);
    // L5: 128->128
    k_gemm<<<g128, 256>>>(bufB, W5, bufA, 128, 128, nullptr, 0);
    k_agg<128><<<aggBlocks, 256>>>(bufA, bufB, b5, 1);
    // L6: 128->64, no relu
    k_gemm<<<g64, 256>>>(bufB, W6, bufA, 128, 64, nullptr, 0);
    k_agg<64><<<aggBlocks, 256>>>(bufA, bufB, b6, 0);

    // pooling + head
    k_pool<<<(N_NODES * 16 + TB - 1) / TB, TB>>>(bufB, batch);
    k_cnt<<<gN, TB>>>(batch);
    k_final<<<N_GRAPHS, 64>>>(Wlin, blin, out);
}

// round 2
// speedup vs baseline: 1.2551x; 1.2551x over previous
#include <cuda_runtime.h>
#include <math.h>

#define N_NODES  100000
#define N_EDGES  3200000
#define N_GRAPHS 512
#define NBLK     98          // ceil(100000/1024)

// ---------------- scratch (static device globals; no allocation) ----------------
__device__ float g_bufA[(size_t)N_NODES * 256];
__device__ float g_bufB[(size_t)N_NODES * 256];
__device__ int   g_deg[N_NODES];
__device__ float g_dinv[N_NODES];
__device__ int   g_rowptr[N_NODES + 1];
__device__ int   g_cursor[N_NODES];
__device__ int   g_col[N_EDGES];
__device__ int   g_bsum[128];
__device__ float g_pool[N_GRAPHS * 64];
__device__ int   g_cnt[N_GRAPHS];

// ---------------- f32x2 helpers ----------------
typedef unsigned long long u64;

__device__ __forceinline__ u64 f2pack(float x, float y) {
    u64 r; asm("mov.b64 %0, {%1, %2};" : "=l"(r) : "f"(x), "f"(y)); return r;
}
__device__ __forceinline__ u64 f2dup(float x) {
    u64 r; asm("mov.b64 %0, {%1, %1};" : "=l"(r) : "f"(x)); return r;
}
__device__ __forceinline__ void f2fma(u64& d, u64 a, u64 b) {
    asm("fma.rn.f32x2 %0, %1, %2, %0;" : "+l"(d) : "l"(a), "l"(b));
}
__device__ __forceinline__ void f2unpack(u64 v, float& lo, float& hi) {
    asm("mov.b64 {%0, %1}, %2;" : "=f"(lo), "=f"(hi) : "l"(v));
}

// ---------------- init ----------------
__global__ void k_init() {
    int i = blockIdx.x * blockDim.x + threadIdx.x;
    if (i < N_NODES) g_deg[i] = 1;               // self loop
    if (i < N_GRAPHS * 64) g_pool[i] = 0.f;
    if (i < N_GRAPHS) g_cnt[i] = 0;
}

// ---------------- degree histogram over dst ----------------
__global__ void k_hist(const int* __restrict__ dst) {
    int i = blockIdx.x * blockDim.x + threadIdx.x;
    if (i < N_EDGES) atomicAdd(&g_deg[dst[i]], 1);
}

// ---------------- 3-phase multi-block exclusive scan of (deg-1) ----------------
__global__ void k_scan1() {               // grid NBLK, block 1024
    __shared__ int ws[32];
    int t = threadIdx.x;
    int i = blockIdx.x * 1024 + t;
    int v = (i < N_NODES) ? (g_deg[i] - 1) : 0;
    int lane = t & 31, wid = t >> 5;
    int x = v;
#pragma unroll
    for (int off = 1; off < 32; off <<= 1) {
        int y = __shfl_up_sync(0xffffffffu, x, off);
        if (lane >= off) x += y;
    }
    if (lane == 31) ws[wid] = x;
    __syncthreads();
    if (wid == 0) {
        int s = ws[lane];
#pragma unroll
        for (int off = 1; off < 32; off <<= 1) {
            int y = __shfl_up_sync(0xffffffffu, s, off);
            if (lane >= off) s += y;
        }
        ws[lane] = s;
    }
    __syncthreads();
    int excl = (wid ? ws[wid - 1] : 0) + (x - v);
    if (i < N_NODES) g_rowptr[i] = excl;
    if (t == 0) g_bsum[blockIdx.x] = ws[31];
}

__global__ void k_scan2() {               // 1 block, 128 threads
    __shared__ int ws[4];
    int t = threadIdx.x;
    int v = (t < NBLK) ? g_bsum[t] : 0;
    int lane = t & 31, wid = t >> 5;
    int x = v;
#pragma unroll
    for (int off = 1; off < 32; off <<= 1) {
        int y = __shfl_up_sync(0xffffffffu, x, off);
        if (lane >= off) x += y;
    }
    if (lane == 31) ws[wid] = x;
    __syncthreads();
    int add = 0;
    for (int w = 0; w < wid; w++) add += ws[w];
    if (t < NBLK) g_bsum[t] = add + x - v;
}

__global__ void k_scan3() {               // grid NBLK, block 1024: add offsets, init cursor+dinv
    int i = blockIdx.x * 1024 + threadIdx.x;
    if (i < N_NODES) {
        int v = g_rowptr[i] + g_bsum[blockIdx.x];
        g_rowptr[i] = v;
        g_cursor[i] = v;
        g_dinv[i] = rsqrtf((float)g_deg[i]);
    }
    if (i == 0) g_rowptr[N_NODES] = N_EDGES;
}

__global__ void k_fill(const int* __restrict__ src, const int* __restrict__ dst) {
    int i = blockIdx.x * blockDim.x + threadIdx.x;
    if (i < N_EDGES) {
        int d = dst[i];
        int p = atomicAdd(&g_cursor[d], 1);
        g_col[p] = src[i];
    }
}

// ---------------- f32x2 GEMM: Out[N,Cn] = A[N,K] @ W[K,Cn] (+bias, relu) ----------------
// tile 128x64x16, 256 threads, 8x4 microtile (4 row-pair f32x2 x 4 cols)
__global__ __launch_bounds__(256) void k_gemm(const float* __restrict__ A,
                                              const float* __restrict__ W,
                                              float* __restrict__ Out,
                                              int K, int Cn,
                                              const float* __restrict__ bias, int relu) {
    const int BM = 128, BN = 64, BK = 16;
    __shared__ float As[BK][BM + 4];
    __shared__ float Ws[BK][BN + 4];
    int tid = threadIdx.x;
    int tx = tid & 15;            // col group: cols tx*4 .. +3
    int ty = tid >> 4;            // row group: rows ty*8 .. +7
    int row0 = blockIdx.y * BM, col0 = blockIdx.x * BN;

    u64 acc[4][4];
#pragma unroll
    for (int i = 0; i < 4; i++)
#pragma unroll
        for (int j = 0; j < 4; j++) acc[i][j] = 0ULL;

    int wkr = tid >> 4, wcq = tid & 15;   // W loader

    for (int kk = 0; kk < K; kk += BK) {
        // load A tile (128 rows x 16 k), 512 float4 tasks, transposed store
#pragma unroll
        for (int q = tid; q < 512; q += 256) {
            int r = q >> 2, k4 = q & 3;
            int grow = row0 + r;
            float4 v = make_float4(0.f, 0.f, 0.f, 0.f);
            if (grow < N_NODES) v = *(const float4*)(A + (size_t)grow * K + kk + k4 * 4);
            As[k4 * 4 + 0][r] = v.x;
            As[k4 * 4 + 1][r] = v.y;
            As[k4 * 4 + 2][r] = v.z;
            As[k4 * 4 + 3][r] = v.w;
        }
        // load W tile (16 k x 64 cols)
        *(float4*)&Ws[wkr][wcq * 4] =
            *(const float4*)(W + (size_t)(kk + wkr) * Cn + col0 + wcq * 4);
        __syncthreads();
#pragma unroll
        for (int k = 0; k < BK; k++) {
            float4 a0 = *(const float4*)&As[k][ty * 8];
            float4 a1 = *(const float4*)&As[k][ty * 8 + 4];
            float4 b  = *(const float4*)&Ws[k][tx * 4];
            u64 A0 = f2pack(a0.x, a0.y);
            u64 A1 = f2pack(a0.z, a0.w);
            u64 A2 = f2pack(a1.x, a1.y);
            u64 A3 = f2pack(a1.z, a1.w);
            u64 B0 = f2dup(b.x), B1 = f2dup(b.y), B2 = f2dup(b.z), B3 = f2dup(b.w);
            f2fma(acc[0][0], A0, B0); f2fma(acc[0][1], A0, B1);
            f2fma(acc[0][2], A0, B2); f2fma(acc[0][3], A0, B3);
            f2fma(acc[1][0], A1, B0); f2fma(acc[1][1], A1, B1);
            f2fma(acc[1][2], A1, B2); f2fma(acc[1][3], A1, B3);
            f2fma(acc[2][0], A2, B0); f2fma(acc[2][1], A2, B1);
            f2fma(acc[2][2], A2, B2); f2fma(acc[2][3], A2, B3);
            f2fma(acc[3][0], A3, B0); f2fma(acc[3][1], A3, B1);
            f2fma(acc[3][2], A3, B2); f2fma(acc[3][3], A3, B3);
        }
        __syncthreads();
    }

    float4 bb = make_float4(0.f, 0.f, 0.f, 0.f);
    if (bias) bb = *(const float4*)(bias + col0 + tx * 4);
    const float* bp = &bb.x;
#pragma unroll
    for (int i = 0; i < 4; i++) {
        int r0 = row0 + ty * 8 + i * 2;
        float lo[4], hi[4];
#pragma unroll
        for (int j = 0; j < 4; j++) {
            f2unpack(acc[i][j], lo[j], hi[j]);
            lo[j] += bp[j]; hi[j] += bp[j];
            if (relu) { lo[j] = fmaxf(lo[j], 0.f); hi[j] = fmaxf(hi[j], 0.f); }
        }
        if (r0 < N_NODES)
            *(float4*)(Out + (size_t)r0 * Cn + col0 + tx * 4) = make_float4(lo[0], lo[1], lo[2], lo[3]);
        if (r0 + 1 < N_NODES)
            *(float4*)(Out + (size_t)(r0 + 1) * Cn + col0 + tx * 4) = make_float4(hi[0], hi[1], hi[2], hi[3]);
    }
}

// ---------------- CSR aggregation, channel-strided ----------------
// O[n, choff:choff+CW] = dinv[n]*(sum dinv[u]*T[u] + dinv[n]*T[n]) + b ; one warp/node
template <int CW>
__global__ void k_agg(const float* __restrict__ T, float* __restrict__ O,
                      const float* __restrict__ bias, int relu, int stride, int choff) {
    int warp = threadIdx.x >> 5;
    int lane = threadIdx.x & 31;
    int n = blockIdx.x * 8 + warp;
    float dn = g_dinv[n];
    int s = g_rowptr[n], e = g_rowptr[n + 1];

    if (CW == 128) {
        int o0 = choff + lane * 4;
        float4 a = *(const float4*)(T + (size_t)n * stride + o0);
        a.x *= dn; a.y *= dn; a.z *= dn; a.w *= dn;
        int j = s;
        for (; j + 1 < e; j += 2) {
            int u0 = g_col[j], u1 = g_col[j + 1];
            float w0 = g_dinv[u0], w1 = g_dinv[u1];
            float4 v0 = *(const float4*)(T + (size_t)u0 * stride + o0);
            float4 v1 = *(const float4*)(T + (size_t)u1 * stride + o0);
            a.x += w0 * v0.x + w1 * v1.x;
            a.y += w0 * v0.y + w1 * v1.y;
            a.z += w0 * v0.z + w1 * v1.z;
            a.w += w0 * v0.w + w1 * v1.w;
        }
        if (j < e) {
            int u = g_col[j];
            float w = g_dinv[u];
            float4 v = *(const float4*)(T + (size_t)u * stride + o0);
            a.x += w * v.x; a.y += w * v.y; a.z += w * v.z; a.w += w * v.w;
        }
        float4 b0 = make_float4(0.f, 0.f, 0.f, 0.f);
        if (bias) b0 = *(const float4*)(bias + o0);
        float4 r;
        r.x = dn * a.x + b0.x; r.y = dn * a.y + b0.y;
        r.z = dn * a.z + b0.z; r.w = dn * a.w + b0.w;
        if (relu) {
            r.x = fmaxf(r.x, 0.f); r.y = fmaxf(r.y, 0.f);
            r.z = fmaxf(r.z, 0.f); r.w = fmaxf(r.w, 0.f);
        }
        *(float4*)(O + (size_t)n * stride + o0) = r;
    } else { // CW == 64
        int o0 = choff + lane * 2;
        float2 a = *(const float2*)(T + (size_t)n * stride + o0);
        a.x *= dn; a.y *= dn;
        int j = s;
        for (; j + 1 < e; j += 2) {
            int u0 = g_col[j], u1 = g_col[j + 1];
            float w0 = g_dinv[u0], w1 = g_dinv[u1];
            float2 v0 = *(const float2*)(T + (size_t)u0 * stride + o0);
            float2 v1 = *(const float2*)(T + (size_t)u1 * stride + o0);
            a.x += w0 * v0.x + w1 * v1.x;
            a.y += w0 * v0.y + w1 * v1.y;
        }
        if (j < e) {
            int u = g_col[j];
            float w = g_dinv[u];
            float2 v = *(const float2*)(T + (size_t)u * stride + o0);
            a.x += w * v.x; a.y += w * v.y;
        }
        float2 b0 = make_float2(0.f, 0.f);
        if (bias) b0 = *(const float2*)(bias + o0);
        float rx = dn * a.x + b0.x, ry = dn * a.y + b0.y;
        if (relu) { rx = fmaxf(rx, 0.f); ry = fmaxf(ry, 0.f); }
        *(float2*)(O + (size_t)n * stride + o0) = make_float2(rx, ry);
    }
}

// ---------------- pooling ----------------
__global__ void k_pool(const float* __restrict__ h, const int* __restrict__ batch) {
    int idx = blockIdx.x * blockDim.x + threadIdx.x;
    if (idx >= N_NODES * 16) return;
    int n = idx >> 4, q = idx & 15;
    int g = batch[n];
    float4 v = *(const float4*)(h + (size_t)n * 64 + q * 4);
    float* p = g_pool + g * 64 + q * 4;
    atomicAdd(p + 0, v.x);
    atomicAdd(p + 1, v.y);
    atomicAdd(p + 2, v.z);
    atomicAdd(p + 3, v.w);
}

__global__ void k_cnt(const int* __restrict__ batch) {
    int i = blockIdx.x * blockDim.x + threadIdx.x;
    if (i < N_NODES) atomicAdd(&g_cnt[batch[i]], 1);
}

// ---------------- head ----------------
__global__ void k_final(const float* __restrict__ Wlin, const float* __restrict__ blin,
                        float* __restrict__ out) {
    int g = blockIdx.x;
    int t = threadIdx.x;  // 64 threads
    __shared__ float mean[64];
    __shared__ float logits[10];
    __shared__ float red2[2];
    float c = (float)g_cnt[g];
    float inv = 1.0f / fmaxf(c, 1.0f);
    mean[t] = g_pool[g * 64 + t] * inv;
    __syncthreads();
    if (t < 10) {
        float s = blin[t];
        for (int k = 0; k < 64; k++) s += mean[k] * Wlin[k * 10 + t];
        logits[t] = s;
    }
    __syncthreads();
    if (t == 0) {
        float mx = logits[0];
        for (int l = 1; l < 10; l++) mx = fmaxf(mx, logits[l]);
        float se = 0.f;
        for (int l = 0; l < 10; l++) se += expf(logits[l] - mx);
        red2[0] = mx;
        red2[1] = se;
    }
    __syncthreads();
    if (t < 10) {
        float lsm = logits[t] - red2[0] - logf(red2[1]);
        out[g * 10 + t] = lsm;
        out[N_GRAPHS * 10 + g * 10 + t] = expf(lsm);
    }
}

// ---------------- launch ----------------
extern "C" void kernel_launch(void* const* d_in, const int* in_sizes, int n_in,
                              void* d_out, int out_size) {
    const float* x     = (const float*)d_in[0];
    const int*   ei    = (const int*)d_in[1];
    const int*   batch = (const int*)d_in[2];
    const float* W1 = (const float*)d_in[4];  const float* b1 = (const float*)d_in[5];
    const float* W2 = (const float*)d_in[6];  const float* b2 = (const float*)d_in[7];
    const float* W3 = (const float*)d_in[8];  const float* b3 = (const float*)d_in[9];
    const float* W4 = (const float*)d_in[10]; const float* b4 = (const float*)d_in[11];
    const float* W5 = (const float*)d_in[12]; const float* b5 = (const float*)d_in[13];
    const float* W6 = (const float*)d_in[14]; const float* b6 = (const float*)d_in[15];
    const float* Wlin = (const float*)d_in[16];
    const float* blin = (const float*)d_in[17];
    const int* src = ei;
    const int* dst = ei + N_EDGES;
    float* out = (float*)d_out;

    float *bufA, *bufB;
    cudaGetSymbolAddress((void**)&bufA, g_bufA);
    cudaGetSymbolAddress((void**)&bufB, g_bufB);

    const int TB = 256;
    int gN = (N_NODES + TB - 1) / TB;
    int gE = (N_EDGES + TB - 1) / TB;

    // preprocessing
    k_init<<<gN, TB>>>();
    k_hist<<<gE, TB>>>(dst);
    k_scan1<<<NBLK, 1024>>>();
    k_scan2<<<1, 128>>>();
    k_scan3<<<NBLK, 1024>>>();
    k_fill<<<gE, TB>>>(src, dst);

    int aggBlocks = N_NODES / 8;
    dim3 g256(4, 782), g128(2, 782), g64(1, 782);

    // L1: aggregate-first (128 ch), then GEMM 128->256 (+bias+relu)
    k_agg<128><<<aggBlocks, 256>>>(x, bufA, nullptr, 0, 128, 0);
    k_gemm<<<g256, 256>>>(bufA, W1, bufB, 128, 256, b1, 1);
    // L2: transform-first, split agg
    k_gemm<<<g256, 256>>>(bufB, W2, bufA, 256, 256, nullptr, 0);
    k_agg<128><<<aggBlocks, 256>>>(bufA, bufB, b2, 1, 256, 0);
    k_agg<128><<<aggBlocks, 256>>>(bufA, bufB, b2, 1, 256, 128);
    // L3
    k_gemm<<<g256, 256>>>(bufB, W3, bufA, 256, 256, nullptr, 0);
    k_agg<128><<<aggBlocks, 256>>>(bufA, bufB, b3, 1, 256, 0);
    k_agg<128><<<aggBlocks, 256>>>(bufA, bufB, b3, 1, 256, 128);
    // L4: 256->128
    k_gemm<<<g128, 256>>>(bufB, W4, bufA, 256, 128, nullptr, 0);
    k_agg<128><<<aggBlocks, 256>>>(bufA, bufB, b4, 1, 128, 0);
    // L5: 128->128
    k_gemm<<<g128, 256>>>(bufB, W5, bufA, 128, 128, nullptr, 0);
    k_agg<128><<<aggBlocks, 256>>>(bufA, bufB, b5, 1, 128, 0);
    // L6: 128->64, no relu
    k_gemm<<<g64, 256>>>(bufB, W6, bufA, 128, 64, nullptr, 0);
    k_agg<64><<<aggBlocks, 256>>>(bufA, bufB, b6, 0, 64, 0);

    // pooling + head
    k_pool<<<(N_NODES * 16 + TB - 1) / TB, TB>>>(bufB, batch);
    k_cnt<<<gN, TB>>>(batch);
    k_final<<<N_GRAPHS, 64>>>(Wlin, blin, out);
}

// round 3
// speedup vs baseline: 1.3692x; 1.0909x over previous
#include <cuda_runtime.h>
#include <cuda_fp16.h>
#include <math.h>

#define N_NODES  100000
#define N_EDGES  3200000
#define N_GRAPHS 512
#define NBLK     98          // ceil(100000/1024)

// ---------------- scratch (static device globals; no allocation) ----------------
__device__ __half g_hA[(size_t)N_NODES * 256];
__device__ __half g_hB[(size_t)N_NODES * 256];
__device__ float  g_h6[(size_t)N_NODES * 64];   // final layer output (fp32 for pooling)
__device__ int    g_deg[N_NODES];
__device__ float  g_dinv[N_NODES];
__device__ int    g_rowptr[N_NODES + 1];
__device__ int    g_cursor[N_NODES];
__device__ int    g_col[N_EDGES];
__device__ int    g_bsum[128];
__device__ float  g_pool[N_GRAPHS * 64];
__device__ int    g_cnt[N_GRAPHS];

// ---------------- f32x2 helpers ----------------
typedef unsigned long long u64;

__device__ __forceinline__ u64 f2pack(float x, float y) {
    u64 r; asm("mov.b64 %0, {%1, %2};" : "=l"(r) : "f"(x), "f"(y)); return r;
}
__device__ __forceinline__ u64 f2dup(float x) {
    u64 r; asm("mov.b64 %0, {%1, %1};" : "=l"(r) : "f"(x)); return r;
}
__device__ __forceinline__ void f2fma(u64& d, u64 a, u64 b) {
    asm("fma.rn.f32x2 %0, %1, %2, %0;" : "+l"(d) : "l"(a), "l"(b));
}
__device__ __forceinline__ void f2unpack(u64 v, float& lo, float& hi) {
    asm("mov.b64 {%0, %1}, %2;" : "=f"(lo), "=f"(hi) : "l"(v));
}

// ---------------- init ----------------
__global__ void k_init() {
    int i = blockIdx.x * blockDim.x + threadIdx.x;
    if (i < N_NODES) g_deg[i] = 1;               // self loop
    if (i < N_GRAPHS * 64) g_pool[i] = 0.f;
    if (i < N_GRAPHS) g_cnt[i] = 0;
}

// ---------------- x -> half ----------------
__global__ void k_tohalf(const float* __restrict__ x) {
    int i = blockIdx.x * blockDim.x + threadIdx.x;   // one float4 -> 4 halves
    if (i >= N_NODES * 32) return;
    float4 v = *(const float4*)(x + (size_t)i * 4);
    __half2 h0 = __floats2half2_rn(v.x, v.y);
    __half2 h1 = __floats2half2_rn(v.z, v.w);
    uint2 o; o.x = *(unsigned*)&h0; o.y = *(unsigned*)&h1;
    *(uint2*)(g_hA + (size_t)i * 4) = o;
}

// ---------------- degree histogram over dst ----------------
__global__ void k_hist(const int* __restrict__ dst) {
    int i = blockIdx.x * blockDim.x + threadIdx.x;
    if (i < N_EDGES) atomicAdd(&g_deg[dst[i]], 1);
}

// ---------------- 3-phase multi-block exclusive scan of (deg-1) ----------------
__global__ void k_scan1() {
    __shared__ int ws[32];
    int t = threadIdx.x;
    int i = blockIdx.x * 1024 + t;
    int v = (i < N_NODES) ? (g_deg[i] - 1) : 0;
    int lane = t & 31, wid = t >> 5;
    int x = v;
#pragma unroll
    for (int off = 1; off < 32; off <<= 1) {
        int y = __shfl_up_sync(0xffffffffu, x, off);
        if (lane >= off) x += y;
    }
    if (lane == 31) ws[wid] = x;
    __syncthreads();
    if (wid == 0) {
        int s = ws[lane];
#pragma unroll
        for (int off = 1; off < 32; off <<= 1) {
            int y = __shfl_up_sync(0xffffffffu, s, off);
            if (lane >= off) s += y;
        }
        ws[lane] = s;
    }
    __syncthreads();
    int excl = (wid ? ws[wid - 1] : 0) + (x - v);
    if (i < N_NODES) g_rowptr[i] = excl;
    if (t == 0) g_bsum[blockIdx.x] = ws[31];
}

__global__ void k_scan2() {
    __shared__ int ws[4];
    int t = threadIdx.x;
    int v = (t < NBLK) ? g_bsum[t] : 0;
    int lane = t & 31, wid = t >> 5;
    int x = v;
#pragma unroll
    for (int off = 1; off < 32; off <<= 1) {
        int y = __shfl_up_sync(0xffffffffu, x, off);
        if (lane >= off) x += y;
    }
    if (lane == 31) ws[wid] = x;
    __syncthreads();
    int add = 0;
    for (int w = 0; w < wid; w++) add += ws[w];
    if (t < NBLK) g_bsum[t] = add + x - v;
}

__global__ void k_scan3() {
    int i = blockIdx.x * 1024 + threadIdx.x;
    if (i < N_NODES) {
        int v = g_rowptr[i] + g_bsum[blockIdx.x];
        g_rowptr[i] = v;
        g_cursor[i] = v;
        g_dinv[i] = rsqrtf((float)g_deg[i]);
    }
    if (i == 0) g_rowptr[N_NODES] = N_EDGES;
}

__global__ void k_fill(const int* __restrict__ src, const int* __restrict__ dst) {
    int i = blockIdx.x * blockDim.x + threadIdx.x;
    if (i < N_EDGES) {
        int d = dst[i];
        int p = atomicAdd(&g_cursor[d], 1);
        g_col[p] = src[i];
    }
}

// ---------------- f32x2 GEMM, half A operand: Out[N,Cn](half) = A[N,K](half) @ W[K,Cn](f32) ----------------
// tile 128x64x16, 256 threads, 8x4 microtile
__global__ __launch_bounds__(256) void k_gemm(const __half* __restrict__ A,
                                              const float* __restrict__ W,
                                              __half* __restrict__ Out,
                                              int K, int Cn,
                                              const float* __restrict__ bias, int relu) {
    const int BM = 128, BN = 64, BK = 16;
    __shared__ float As[BK][BM + 4];
    __shared__ float Ws[BK][BN + 4];
    int tid = threadIdx.x;
    int tx = tid & 15;
    int ty = tid >> 4;
    int row0 = blockIdx.y * BM, col0 = blockIdx.x * BN;

    u64 acc[4][4];
#pragma unroll
    for (int i = 0; i < 4; i++)
#pragma unroll
        for (int j = 0; j < 4; j++) acc[i][j] = 0ULL;

    int lr = tid >> 1, lp = tid & 1;      // A loader: row lr, 8-half part lp
    int wkr = tid >> 4, wcq = tid & 15;   // W loader
    int grow = row0 + lr;
    bool avalid = grow < N_NODES;
    const __half* Aptr = A + (size_t)(avalid ? grow : 0) * K + lp * 8;

    for (int kk = 0; kk < K; kk += BK) {
        uint4 v = make_uint4(0u, 0u, 0u, 0u);
        if (avalid) v = *(const uint4*)(Aptr + kk);
        const __half2* hp = (const __half2*)&v;
#pragma unroll
        for (int i = 0; i < 4; i++) {
            float2 f = __half22float2(hp[i]);
            As[lp * 8 + i * 2 + 0][lr] = f.x;
            As[lp * 8 + i * 2 + 1][lr] = f.y;
        }
        *(float4*)&Ws[wkr][wcq * 4] =
            *(const float4*)(W + (size_t)(kk + wkr) * Cn + col0 + wcq * 4);
        __syncthreads();
#pragma unroll
        for (int k = 0; k < BK; k++) {
            float4 a0 = *(const float4*)&As[k][ty * 8];
            float4 a1 = *(const float4*)&As[k][ty * 8 + 4];
            float4 b  = *(const float4*)&Ws[k][tx * 4];
            u64 A0 = f2pack(a0.x, a0.y);
            u64 A1 = f2pack(a0.z, a0.w);
            u64 A2 = f2pack(a1.x, a1.y);
            u64 A3 = f2pack(a1.z, a1.w);
            u64 B0 = f2dup(b.x), B1 = f2dup(b.y), B2 = f2dup(b.z), B3 = f2dup(b.w);
            f2fma(acc[0][0], A0, B0); f2fma(acc[0][1], A0, B1);
            f2fma(acc[0][2], A0, B2); f2fma(acc[0][3], A0, B3);
            f2fma(acc[1][0], A1, B0); f2fma(acc[1][1], A1, B1);
            f2fma(acc[1][2], A1, B2); f2fma(acc[1][3], A1, B3);
            f2fma(acc[2][0], A2, B0); f2fma(acc[2][1], A2, B1);
            f2fma(acc[2][2], A2, B2); f2fma(acc[2][3], A2, B3);
            f2fma(acc[3][0], A3, B0); f2fma(acc[3][1], A3, B1);
            f2fma(acc[3][2], A3, B2); f2fma(acc[3][3], A3, B3);
        }
        __syncthreads();
    }

    float4 bb = make_float4(0.f, 0.f, 0.f, 0.f);
    if (bias) bb = *(const float4*)(bias + col0 + tx * 4);
    const float* bp = &bb.x;
#pragma unroll
    for (int i = 0; i < 4; i++) {
        int r0 = row0 + ty * 8 + i * 2;
        float lo[4], hi[4];
#pragma unroll
        for (int j = 0; j < 4; j++) {
            f2unpack(acc[i][j], lo[j], hi[j]);
            lo[j] += bp[j]; hi[j] += bp[j];
            if (relu) { lo[j] = fmaxf(lo[j], 0.f); hi[j] = fmaxf(hi[j], 0.f); }
        }
        if (r0 < N_NODES) {
            __half2 p0 = __floats2half2_rn(lo[0], lo[1]);
            __half2 p1 = __floats2half2_rn(lo[2], lo[3]);
            uint2 o; o.x = *(unsigned*)&p0; o.y = *(unsigned*)&p1;
            *(uint2*)(Out + (size_t)r0 * Cn + col0 + tx * 4) = o;
        }
        if (r0 + 1 < N_NODES) {
            __half2 p0 = __floats2half2_rn(hi[0], hi[1]);
            __half2 p1 = __floats2half2_rn(hi[2], hi[3]);
            uint2 o; o.x = *(unsigned*)&p0; o.y = *(unsigned*)&p1;
            *(uint2*)(Out + (size_t)(r0 + 1) * Cn + col0 + tx * 4) = o;
        }
    }
}

// ---------------- CSR aggregation over half features ----------------
// one warp per node; accumulate fp32; OUTF: write fp32 (final layer) else half
template <int CW, bool OUTF>
__global__ void k_agg(const __half* __restrict__ T, void* __restrict__ Optr,
                      const float* __restrict__ bias, int relu, int stride, int choff) {
    int warp = threadIdx.x >> 5;
    int lane = threadIdx.x & 31;
    int n = blockIdx.x * 8 + warp;
    float dn = g_dinv[n];
    int s = g_rowptr[n], e = g_rowptr[n + 1];

    if (CW == 128) {
        int o0 = choff + lane * 4;
        const __half* self = T + (size_t)n * stride + o0;
        uint2 raw = *(const uint2*)self;
        float2 f0 = __half22float2(*(__half2*)&raw.x);
        float2 f1 = __half22float2(*(__half2*)&raw.y);
        float ax = f0.x * dn, ay = f0.y * dn, az = f1.x * dn, aw = f1.y * dn;
        int j = s;
        for (; j + 1 < e; j += 2) {
            int u0 = g_col[j], u1 = g_col[j + 1];
            float w0 = g_dinv[u0], w1 = g_dinv[u1];
            uint2 r0 = *(const uint2*)(T + (size_t)u0 * stride + o0);
            uint2 r1 = *(const uint2*)(T + (size_t)u1 * stride + o0);
            float2 a0 = __half22float2(*(__half2*)&r0.x);
            float2 a1 = __half22float2(*(__half2*)&r0.y);
            float2 b0 = __half22float2(*(__half2*)&r1.x);
            float2 b1 = __half22float2(*(__half2*)&r1.y);
            ax += w0 * a0.x + w1 * b0.x;
            ay += w0 * a0.y + w1 * b0.y;
            az += w0 * a1.x + w1 * b1.x;
            aw += w0 * a1.y + w1 * b1.y;
        }
        if (j < e) {
            int u = g_col[j];
            float w = g_dinv[u];
            uint2 r0 = *(const uint2*)(T + (size_t)u * stride + o0);
            float2 a0 = __half22float2(*(__half2*)&r0.x);
            float2 a1 = __half22float2(*(__half2*)&r0.y);
            ax += w * a0.x; ay += w * a0.y; az += w * a1.x; aw += w * a1.y;
        }
        float4 b0 = make_float4(0.f, 0.f, 0.f, 0.f);
        if (bias) b0 = *(const float4*)(bias + o0);
        float rx = dn * ax + b0.x, ry = dn * ay + b0.y;
        float rz = dn * az + b0.z, rw = dn * aw + b0.w;
        if (relu) {
            rx = fmaxf(rx, 0.f); ry = fmaxf(ry, 0.f);
            rz = fmaxf(rz, 0.f); rw = fmaxf(rw, 0.f);
        }
        if (OUTF) {
            *(float4*)((float*)Optr + (size_t)n * stride + o0) = make_float4(rx, ry, rz, rw);
        } else {
            __half2 p0 = __floats2half2_rn(rx, ry);
            __half2 p1 = __floats2half2_rn(rz, rw);
            uint2 o; o.x = *(unsigned*)&p0; o.y = *(unsigned*)&p1;
            *(uint2*)((__half*)Optr + (size_t)n * stride + o0) = o;
        }
    } else { // CW == 64
        int o0 = choff + lane * 2;
        unsigned raw = *(const unsigned*)(T + (size_t)n * stride + o0);
        float2 f0 = __half22float2(*(__half2*)&raw);
        float ax = f0.x * dn, ay = f0.y * dn;
        int j = s;
        for (; j + 1 < e; j += 2) {
            int u0 = g_col[j], u1 = g_col[j + 1];
            float w0 = g_dinv[u0], w1 = g_dinv[u1];
            unsigned r0 = *(const unsigned*)(T + (size_t)u0 * stride + o0);
            unsigned r1 = *(const unsigned*)(T + (size_t)u1 * stride + o0);
            float2 a0 = __half22float2(*(__half2*)&r0);
            float2 b0 = __half22float2(*(__half2*)&r1);
            ax += w0 * a0.x + w1 * b0.x;
            ay += w0 * a0.y + w1 * b0.y;
        }
        if (j < e) {
            int u = g_col[j];
            float w = g_dinv[u];
            unsigned r0 = *(const unsigned*)(T + (size_t)u * stride + o0);
            float2 a0 = __half22float2(*(__half2*)&r0);
            ax += w * a0.x; ay += w * a0.y;
        }
        float2 b0 = make_float2(0.f, 0.f);
        if (bias) b0 = *(const float2*)(bias + o0);
        float rx = dn * ax + b0.x, ry = dn * ay + b0.y;
        if (relu) { rx = fmaxf(rx, 0.f); ry = fmaxf(ry, 0.f); }
        if (OUTF) {
            *(float2*)((float*)Optr + (size_t)n * stride + o0) = make_float2(rx, ry);
        } else {
            __half2 p0 = __floats2half2_rn(rx, ry);
            *(unsigned*)((__half*)Optr + (size_t)n * stride + o0) = *(unsigned*)&p0;
        }
    }
}

// ---------------- pooling ----------------
__global__ void k_pool(const float* __restrict__ h, const int* __restrict__ batch) {
    int idx = blockIdx.x * blockDim.x + threadIdx.x;
    if (idx >= N_NODES * 16) return;
    int n = idx >> 4, q = idx & 15;
    int g = batch[n];
    float4 v = *(const float4*)(h + (size_t)n * 64 + q * 4);
    float* p = g_pool + g * 64 + q * 4;
    atomicAdd(p + 0, v.x);
    atomicAdd(p + 1, v.y);
    atomicAdd(p + 2, v.z);
    atomicAdd(p + 3, v.w);
}

__global__ void k_cnt(const int* __restrict__ batch) {
    int i = blockIdx.x * blockDim.x + threadIdx.x;
    if (i < N_NODES) atomicAdd(&g_cnt[batch[i]], 1);
}

// ---------------- head ----------------
__global__ void k_final(const float* __restrict__ Wlin, const float* __restrict__ blin,
                        float* __restrict__ out) {
    int g = blockIdx.x;
    int t = threadIdx.x;  // 64 threads
    __shared__ float mean[64];
    __shared__ float logits[10];
    __shared__ float red2[2];
    float c = (float)g_cnt[g];
    float inv = 1.0f / fmaxf(c, 1.0f);
    mean[t] = g_pool[g * 64 + t] * inv;
    __syncthreads();
    if (t < 10) {
        float s = blin[t];
        for (int k = 0; k < 64; k++) s += mean[k] * Wlin[k * 10 + t];
        logits[t] = s;
    }
    __syncthreads();
    if (t == 0) {
        float mx = logits[0];
        for (int l = 1; l < 10; l++) mx = fmaxf(mx, logits[l]);
        float se = 0.f;
        for (int l = 0; l < 10; l++) se += expf(logits[l] - mx);
        red2[0] = mx;
        red2[1] = se;
    }
    __syncthreads();
    if (t < 10) {
        float lsm = logits[t] - red2[0] - logf(red2[1]);
        out[g * 10 + t] = lsm;
        out[N_GRAPHS * 10 + g * 10 + t] = expf(lsm);
    }
}

// ---------------- launch ----------------
extern "C" void kernel_launch(void* const* d_in, const int* in_sizes, int n_in,
                              void* d_out, int out_size) {
    const float* x     = (const float*)d_in[0];
    const int*   ei    = (const int*)d_in[1];
    const int*   batch = (const int*)d_in[2];
    const float* W1 = (const float*)d_in[4];  const float* b1 = (const float*)d_in[5];
    const float* W2 = (const float*)d_in[6];  const float* b2 = (const float*)d_in[7];
    const float* W3 = (const float*)d_in[8];  const float* b3 = (const float*)d_in[9];
    const float* W4 = (const float*)d_in[10]; const float* b4 = (const float*)d_in[11];
    const float* W5 = (const float*)d_in[12]; const float* b5 = (const float*)d_in[13];
    const float* W6 = (const float*)d_in[14]; const float* b6 = (const float*)d_in[15];
    const float* Wlin = (const float*)d_in[16];
    const float* blin = (const float*)d_in[17];
    const int* src = ei;
    const int* dst = ei + N_EDGES;
    float* out = (float*)d_out;

    __half *hA, *hB;
    float *h6;
    cudaGetSymbolAddress((void**)&hA, g_hA);
    cudaGetSymbolAddress((void**)&hB, g_hB);
    cudaGetSymbolAddress((void**)&h6, g_h6);

    const int TB = 256;
    int gN = (N_NODES + TB - 1) / TB;
    int gE = (N_EDGES + TB - 1) / TB;

    // preprocessing (+ x -> half into hA)
    k_init<<<gN, TB>>>();
    k_tohalf<<<(N_NODES * 32 + TB - 1) / TB, TB>>>(x);
    k_hist<<<gE, TB>>>(dst);
    k_scan1<<<NBLK, 1024>>>();
    k_scan2<<<1, 128>>>();
    k_scan3<<<NBLK, 1024>>>();
    k_fill<<<gE, TB>>>(src, dst);

    int aggBlocks = N_NODES / 8;
    dim3 g256(4, 782), g128(2, 782), g64(1, 782);

    // L1: aggregate-first (128 ch) on half x, then GEMM 128->256 (+bias+relu)
    k_agg<128, false><<<aggBlocks, 256>>>(hA, hB, nullptr, 0, 128, 0);
    k_gemm<<<g256, 256>>>(hB, W1, hA, 128, 256, b1, 1);
    // L2: transform-first, split agg
    k_gemm<<<g256, 256>>>(hA, W2, hB, 256, 256, nullptr, 0);
    k_agg<128, false><<<aggBlocks, 256>>>(hB, hA, b2, 1, 256, 0);
    k_agg<128, false><<<aggBlocks, 256>>>(hB, hA, b2, 1, 256, 128);
    // L3
    k_gemm<<<g256, 256>>>(hA, W3, hB, 256, 256, nullptr, 0);
    k_agg<128, false><<<aggBlocks, 256>>>(hB, hA, b3, 1, 256, 0);
    k_agg<128, false><<<aggBlocks, 256>>>(hB, hA, b3, 1, 256, 128);
    // L4: 256->128
    k_gemm<<<g128, 256>>>(hA, W4, hB, 256, 128, nullptr, 0);
    k_agg<128, false><<<aggBlocks, 256>>>(hB, hA, b4, 1, 128, 0);
    // L5: 128->128
    k_gemm<<<g128, 256>>>(hA, W5, hB, 128, 128, nullptr, 0);
    k_agg<128, false><<<aggBlocks, 256>>>(hB, hA, b5, 1, 128, 0);
    // L6: 128->64, no relu; agg writes fp32 for pooling
    k_gemm<<<g64, 256>>>(hA, W6, hB, 128, 64, nullptr, 0);
    k_agg<64, true><<<aggBlocks, 256>>>(hB, h6, b6, 0, 64, 0);

    // pooling + head
    k_pool<<<(N_NODES * 16 + TB - 1) / TB, TB>>>(h6, batch);
    k_cnt<<<gN, TB>>>(batch);
    k_final<<<N_GRAPHS, 64>>>(Wlin, blin, out);
}

// round 6
// speedup vs baseline: 1.8499x; 1.3512x over previous
#include <cuda_runtime.h>
#include <cuda_fp16.h>
#include <mma.h>
#include <math.h>

using namespace nvcuda;

#define N_NODES  100000
#define N_EDGES  3200000
#define N_GRAPHS 512
#define NBLK     98          // ceil(100000/1024)

// ---------------- scratch (static device globals; no allocation) ----------------
__device__ __half g_hA[(size_t)N_NODES * 256];
__device__ __half g_hB[(size_t)N_NODES * 256];
__device__ float  g_h6[(size_t)N_NODES * 64];   // final layer output (fp32 for pooling)
__device__ __half g_Wh[262144];                 // all W matrices in half (offsets below)
__device__ int    g_deg[N_NODES];
__device__ float  g_dinv[N_NODES];
__device__ int    g_rowptr[N_NODES + 1];
__device__ int    g_cursor[N_NODES];
__device__ int2   g_cw[N_EDGES];                // packed (src, weight)
__device__ int    g_bsum[128];
__device__ float  g_pool[N_GRAPHS * 64];
__device__ int    g_cnt[N_GRAPHS];

// W offsets in g_Wh
#define OFF_W1 0           // 128*256 = 32768
#define OFF_W2 32768       // 256*256 = 65536
#define OFF_W3 98304       // 65536
#define OFF_W4 163840      // 256*128 = 32768
#define OFF_W5 196608      // 128*128 = 16384
#define OFF_W6 212992      // 128*64  = 8192

// ---------------- init ----------------
__global__ void k_init() {
    int i = blockIdx.x * blockDim.x + threadIdx.x;
    if (i < N_NODES) g_deg[i] = 1;               // self loop
    if (i < N_GRAPHS * 64) g_pool[i] = 0.f;
    if (i < N_GRAPHS) g_cnt[i] = 0;
}

// ---------------- fp32 -> half converts ----------------
__global__ void k_tohalf(const float* __restrict__ x) {
    int i = blockIdx.x * blockDim.x + threadIdx.x;   // one float4 -> 4 halves
    if (i >= N_NODES * 32) return;
    float4 v = *(const float4*)(x + (size_t)i * 4);
    __half2 h0 = __floats2half2_rn(v.x, v.y);
    __half2 h1 = __floats2half2_rn(v.z, v.w);
    uint2 o; o.x = *(unsigned*)&h0; o.y = *(unsigned*)&h1;
    *(uint2*)(g_hA + (size_t)i * 4) = o;
}

__global__ void k_wconv(const float* __restrict__ W, int n, int off) {
    int i = blockIdx.x * blockDim.x + threadIdx.x;
    if (i * 2 < n) {
        float2 v = *(const float2*)(W + i * 2);
        __half2 h = __floats2half2_rn(v.x, v.y);
        *(unsigned*)(g_Wh + off + i * 2) = *(unsigned*)&h;
    }
}

// ---------------- degree histogram over dst ----------------
__global__ void k_hist(const int* __restrict__ dst) {
    int i = blockIdx.x * blockDim.x + threadIdx.x;
    if (i < N_EDGES) atomicAdd(&g_deg[dst[i]], 1);
}

// ---------------- 3-phase multi-block exclusive scan of (deg-1) ----------------
__global__ void k_scan1() {
    __shared__ int ws[32];
    int t = threadIdx.x;
    int i = blockIdx.x * 1024 + t;
    int v = (i < N_NODES) ? (g_deg[i] - 1) : 0;
    int lane = t & 31, wid = t >> 5;
    int x = v;
#pragma unroll
    for (int off = 1; off < 32; off <<= 1) {
        int y = __shfl_up_sync(0xffffffffu, x, off);
        if (lane >= off) x += y;
    }
    if (lane == 31) ws[wid] = x;
    __syncthreads();
    if (wid == 0) {
        int s = ws[lane];
#pragma unroll
        for (int off = 1; off < 32; off <<= 1) {
            int y = __shfl_up_sync(0xffffffffu, s, off);
            if (lane >= off) s += y;
        }
        ws[lane] = s;
    }
    __syncthreads();
    int excl = (wid ? ws[wid - 1] : 0) + (x - v);
    if (i < N_NODES) g_rowptr[i] = excl;
    if (t == 0) g_bsum[blockIdx.x] = ws[31];
}

__global__ void k_scan2() {
    __shared__ int ws[4];
    int t = threadIdx.x;
    int v = (t < NBLK) ? g_bsum[t] : 0;
    int lane = t & 31, wid = t >> 5;
    int x = v;
#pragma unroll
    for (int off = 1; off < 32; off <<= 1) {
        int y = __shfl_up_sync(0xffffffffu, x, off);
        if (lane >= off) x += y;
    }
    if (lane == 31) ws[wid] = x;
    __syncthreads();
    int add = 0;
    for (int w = 0; w < wid; w++) add += ws[w];
    if (t < NBLK) g_bsum[t] = add + x - v;
}

__global__ void k_scan3() {
    int i = blockIdx.x * 1024 + threadIdx.x;
    if (i < N_NODES) {
        int v = g_rowptr[i] + g_bsum[blockIdx.x];
        g_rowptr[i] = v;
        g_cursor[i] = v;
        g_dinv[i] = rsqrtf((float)g_deg[i]);
    }
    if (i == 0) g_rowptr[N_NODES] = N_EDGES;
}

// fill CSR with packed (src, dinv[src]*dinv[dst])
__global__ void k_fill(const int* __restrict__ src, const int* __restrict__ dst) {
    int i = blockIdx.x * blockDim.x + threadIdx.x;
    if (i < N_EDGES) {
        int d = dst[i];
        int s = src[i];
        float w = g_dinv[s] * g_dinv[d];
        int p = atomicAdd(&g_cursor[d], 1);
        g_cw[p] = make_int2(s, __float_as_int(w));
    }
}

// ---------------- wmma GEMM: Out[N,Cn](half) = A[N,K](half) @ Wh[K,Cn](half) + bias, relu ----------------
// tile 128x64, 256 threads (8 warps: 4 M x 2 N), warp tile 32x32 (2x2 m16n16k16 frags)
__global__ __launch_bounds__(256) void k_gemm(const __half* __restrict__ A,
                                              const __half* __restrict__ W,
                                              __half* __restrict__ Out,
                                              int K, int Cn,
                                              const float* __restrict__ bias, int relu) {
    __shared__ __half As[128][24];
    __shared__ __half Ws[16][72];
    __shared__ float  stage[8][1024];

    int tid = threadIdx.x;
    int wid = tid >> 5, lane = tid & 31;
    int wr = wid & 3, wc = wid >> 2;
    int row0 = blockIdx.y * 128, col0 = blockIdx.x * 64;

    wmma::fragment<wmma::accumulator, 16, 16, 16, float> fc[2][2];
#pragma unroll
    for (int i = 0; i < 2; i++)
#pragma unroll
        for (int j = 0; j < 2; j++) wmma::fill_fragment(fc[i][j], 0.f);

    int lr = tid >> 1, lp = tid & 1;
    int grow = row0 + lr;
    bool av = grow < N_NODES;
    const __half* Ap = A + (size_t)(av ? grow : 0) * K + lp * 8;

    for (int kk = 0; kk < K; kk += 16) {
        uint4 v = make_uint4(0u, 0u, 0u, 0u);
        if (av) v = *(const uint4*)(Ap + kk);
        *(uint4*)&As[lr][lp * 8] = v;
        if (tid < 128) {
            int r = tid >> 3, p = tid & 7;
            *(uint4*)&Ws[r][p * 8] =
                *(const uint4*)(W + (size_t)(kk + r) * Cn + col0 + p * 8);
        }
        __syncthreads();
        wmma::fragment<wmma::matrix_a, 16, 16, 16, __half, wmma::row_major> fa[2];
        wmma::fragment<wmma::matrix_b, 16, 16, 16, __half, wmma::row_major> fb[2];
        wmma::load_matrix_sync(fa[0], &As[wr * 32][0], 24);
        wmma::load_matrix_sync(fa[1], &As[wr * 32 + 16][0], 24);
        wmma::load_matrix_sync(fb[0], &Ws[0][wc * 32], 72);
        wmma::load_matrix_sync(fb[1], &Ws[0][wc * 32 + 16], 72);
#pragma unroll
        for (int i = 0; i < 2; i++)
#pragma unroll
            for (int j = 0; j < 2; j++)
                wmma::mma_sync(fc[i][j], fa[i], fb[j], fc[i][j]);
        __syncthreads();
    }

    // epilogue: stage per-warp 32x32 fp32 tile, then bias+relu+half stores
#pragma unroll
    for (int i = 0; i < 2; i++)
#pragma unroll
        for (int j = 0; j < 2; j++)
            wmma::store_matrix_sync(&stage[wid][(i * 16) * 32 + j * 16], fc[i][j], 32,
                                    wmma::mem_row_major);
    __syncwarp();

    int gr = row0 + wr * 32 + lane;
    if (gr < N_NODES) {
        int gc0 = col0 + wc * 32;
        const float* srow = &stage[wid][lane * 32];
        __half* orow = Out + (size_t)gr * Cn + gc0;
#pragma unroll
        for (int q = 0; q < 4; q++) {
            float4 f0 = *(const float4*)(srow + q * 8);
            float4 f1 = *(const float4*)(srow + q * 8 + 4);
            float b[8] = {0, 0, 0, 0, 0, 0, 0, 0};
            if (bias) {
                float4 bb0 = *(const float4*)(bias + gc0 + q * 8);
                float4 bb1 = *(const float4*)(bias + gc0 + q * 8 + 4);
                b[0] = bb0.x; b[1] = bb0.y; b[2] = bb0.z; b[3] = bb0.w;
                b[4] = bb1.x; b[5] = bb1.y; b[6] = bb1.z; b[7] = bb1.w;
            }
            float r[8] = {f0.x + b[0], f0.y + b[1], f0.z + b[2], f0.w + b[3],
                          f1.x + b[4], f1.y + b[5], f1.z + b[6], f1.w + b[7]};
            if (relu) {
#pragma unroll
                for (int q2 = 0; q2 < 8; q2++) r[q2] = fmaxf(r[q2], 0.f);
            }
            __half2 h0 = __floats2half2_rn(r[0], r[1]);
            __half2 h1 = __floats2half2_rn(r[2], r[3]);
            __half2 h2 = __floats2half2_rn(r[4], r[5]);
            __half2 h3 = __floats2half2_rn(r[6], r[7]);
            uint4 o;
            o.x = *(unsigned*)&h0; o.y = *(unsigned*)&h1;
            o.z = *(unsigned*)&h2; o.w = *(unsigned*)&h3;
            *(uint4*)(orow + q * 8) = o;
        }
    }
}

// ---------------- CSR aggregation, lane-cooperative edge fetch + 4-deep gather MLP ----------------
template <int CW, bool OUTF>
__global__ void k_agg(const __half* __restrict__ T, void* __restrict__ Optr,
                      const float* __restrict__ bias, int relu, int stride, int choff) {
    int warp = threadIdx.x >> 5;
    int lane = threadIdx.x & 31;
    int n = blockIdx.x * 8 + warp;
    float dn = g_dinv[n];
    float dn2 = dn * dn;
    int s = g_rowptr[n], e = g_rowptr[n + 1];

    if (CW == 128) {
        int o0 = choff + lane * 4;
        uint2 raw = *(const uint2*)(T + (size_t)n * stride + o0);
        float2 f0 = __half22float2(*(__half2*)&raw.x);
        float2 f1 = __half22float2(*(__half2*)&raw.y);
        float ax = f0.x * dn2, ay = f0.y * dn2, az = f1.x * dn2, aw = f1.y * dn2;

        for (int base = s; base < e; base += 32) {
            int rem = e - base;
            int2 cw = make_int2(0, 0);
            if (lane < rem) cw = g_cw[base + lane];
            int nt = rem < 32 ? rem : 32;
            int t = 0;
            for (; t + 4 <= nt; t += 4) {
                int u0 = __shfl_sync(0xffffffffu, cw.x, t);
                int u1 = __shfl_sync(0xffffffffu, cw.x, t + 1);
                int u2 = __shfl_sync(0xffffffffu, cw.x, t + 2);
                int u3 = __shfl_sync(0xffffffffu, cw.x, t + 3);
                float w0 = __int_as_float(__shfl_sync(0xffffffffu, cw.y, t));
                float w1 = __int_as_float(__shfl_sync(0xffffffffu, cw.y, t + 1));
                float w2 = __int_as_float(__shfl_sync(0xffffffffu, cw.y, t + 2));
                float w3 = __int_as_float(__shfl_sync(0xffffffffu, cw.y, t + 3));
                uint2 r0 = *(const uint2*)(T + (size_t)u0 * stride + o0);
                uint2 r1 = *(const uint2*)(T + (size_t)u1 * stride + o0);
                uint2 r2 = *(const uint2*)(T + (size_t)u2 * stride + o0);
                uint2 r3 = *(const uint2*)(T + (size_t)u3 * stride + o0);
                float2 p0 = __half22float2(*(__half2*)&r0.x), p1 = __half22float2(*(__half2*)&r0.y);
                float2 q0 = __half22float2(*(__half2*)&r1.x), q1 = __half22float2(*(__half2*)&r1.y);
                float2 s0 = __half22float2(*(__half2*)&r2.x), s1 = __half22float2(*(__half2*)&r2.y);
                float2 v0 = __half22float2(*(__half2*)&r3.x), v1 = __half22float2(*(__half2*)&r3.y);
                ax += w0 * p0.x + w1 * q0.x + w2 * s0.x + w3 * v0.x;
                ay += w0 * p0.y + w1 * q0.y + w2 * s0.y + w3 * v0.y;
                az += w0 * p1.x + w1 * q1.x + w2 * s1.x + w3 * v1.x;
                aw += w0 * p1.y + w1 * q1.y + w2 * s1.y + w3 * v1.y;
            }
            for (; t < nt; t++) {
                int u = __shfl_sync(0xffffffffu, cw.x, t);
                float w = __int_as_float(__shfl_sync(0xffffffffu, cw.y, t));
                uint2 r0 = *(const uint2*)(T + (size_t)u * stride + o0);
                float2 p0 = __half22float2(*(__half2*)&r0.x), p1 = __half22float2(*(__half2*)&r0.y);
                ax += w * p0.x; ay += w * p0.y; az += w * p1.x; aw += w * p1.y;
            }
        }
        float4 b0 = make_float4(0.f, 0.f, 0.f, 0.f);
        if (bias) b0 = *(const float4*)(bias + o0);
        float rx = ax + b0.x, ry = ay + b0.y, rz = az + b0.z, rw = aw + b0.w;
        if (relu) {
            rx = fmaxf(rx, 0.f); ry = fmaxf(ry, 0.f);
            rz = fmaxf(rz, 0.f); rw = fmaxf(rw, 0.f);
        }
        if (OUTF) {
            *(float4*)((float*)Optr + (size_t)n * stride + o0) = make_float4(rx, ry, rz, rw);
        } else {
            __half2 p0 = __floats2half2_rn(rx, ry);
            __half2 p1 = __floats2half2_rn(rz, rw);
            uint2 o; o.x = *(unsigned*)&p0; o.y = *(unsigned*)&p1;
            *(uint2*)((__half*)Optr + (size_t)n * stride + o0) = o;
        }
    } else { // CW == 64
        int o0 = choff + lane * 2;
        unsigned raw = *(const unsigned*)(T + (size_t)n * stride + o0);
        float2 f0 = __half22float2(*(__half2*)&raw);
        float ax = f0.x * dn2, ay = f0.y * dn2;
        for (int base = s; base < e; base += 32) {
            int rem = e - base;
            int2 cw = make_int2(0, 0);
            if (lane < rem) cw = g_cw[base + lane];
            int nt = rem < 32 ? rem : 32;
            int t = 0;
            for (; t + 4 <= nt; t += 4) {
                int u0 = __shfl_sync(0xffffffffu, cw.x, t);
                int u1 = __shfl_sync(0xffffffffu, cw.x, t + 1);
                int u2 = __shfl_sync(0xffffffffu, cw.x, t + 2);
                int u3 = __shfl_sync(0xffffffffu, cw.x, t + 3);
                float w0 = __int_as_float(__shfl_sync(0xffffffffu, cw.y, t));
                float w1 = __int_as_float(__shfl_sync(0xffffffffu, cw.y, t + 1));
                float w2 = __int_as_float(__shfl_sync(0xffffffffu, cw.y, t + 2));
                float w3 = __int_as_float(__shfl_sync(0xffffffffu, cw.y, t + 3));
                unsigned r0 = *(const unsigned*)(T + (size_t)u0 * stride + o0);
                unsigned r1 = *(const unsigned*)(T + (size_t)u1 * stride + o0);
                unsigned r2 = *(const unsigned*)(T + (size_t)u2 * stride + o0);
                unsigned r3 = *(const unsigned*)(T + (size_t)u3 * stride + o0);
                float2 p0 = __half22float2(*(__half2*)&r0);
                float2 p1 = __half22float2(*(__half2*)&r1);
                float2 p2 = __half22float2(*(__half2*)&r2);
                float2 p3 = __half22float2(*(__half2*)&r3);
                ax += w0 * p0.x + w1 * p1.x + w2 * p2.x + w3 * p3.x;
                ay += w0 * p0.y + w1 * p1.y + w2 * p2.y + w3 * p3.y;
            }
            for (; t < nt; t++) {
                int u = __shfl_sync(0xffffffffu, cw.x, t);
                float w = __int_as_float(__shfl_sync(0xffffffffu, cw.y, t));
                unsigned r0 = *(const unsigned*)(T + (size_t)u * stride + o0);
                float2 p0 = __half22float2(*(__half2*)&r0);
                ax += w * p0.x; ay += w * p0.y;
            }
        }
        float2 b0 = make_float2(0.f, 0.f);
        if (bias) b0 = *(const float2*)(bias + o0);
        float rx = ax + b0.x, ry = ay + b0.y;
        if (relu) { rx = fmaxf(rx, 0.f); ry = fmaxf(ry, 0.f); }
        if (OUTF) {
            *(float2*)((float*)Optr + (size_t)n * stride + o0) = make_float2(rx, ry);
        } else {
            __half2 p0 = __floats2half2_rn(rx, ry);
            *(unsigned*)((__half*)Optr + (size_t)n * stride + o0) = *(unsigned*)&p0;
        }
    }
}

// ---------------- pooling ----------------
__global__ void k_pool(const float* __restrict__ h, const int* __restrict__ batch) {
    int idx = blockIdx.x * blockDim.x + threadIdx.x;
    if (idx >= N_NODES * 16) return;
    int n = idx >> 4, q = idx & 15;
    int g = batch[n];
    float4 v = *(const float4*)(h + (size_t)n * 64 + q * 4);
    float* p = g_pool + g * 64 + q * 4;
    atomicAdd(p + 0, v.x);
    atomicAdd(p + 1, v.y);
    atomicAdd(p + 2, v.z);
    atomicAdd(p + 3, v.w);
}

__global__ void k_cnt(const int* __restrict__ batch) {
    int i = blockIdx.x * blockDim.x + threadIdx.x;
    if (i < N_NODES) atomicAdd(&g_cnt[batch[i]], 1);
}

// ---------------- head ----------------
__global__ void k_final(const float* __restrict__ Wlin, const float* __restrict__ blin,
                        float* __restrict__ out) {
    int g = blockIdx.x;
    int t = threadIdx.x;  // 64 threads
    __shared__ float mean[64];
    __shared__ float logits[10];
    __shared__ float red2[2];
    float c = (float)g_cnt[g];
    float inv = 1.0f / fmaxf(c, 1.0f);
    mean[t] = g_pool[g * 64 + t] * inv;
    __syncthreads();
    if (t < 10) {
        float s = blin[t];
        for (int k = 0; k < 64; k++) s += mean[k] * Wlin[k * 10 + t];
        logits[t] = s;
    }
    __syncthreads();
    if (t == 0) {
        float mx = logits[0];
        for (int l = 1; l < 10; l++) mx = fmaxf(mx, logits[l]);
        float se = 0.f;
        for (int l = 0; l < 10; l++) se += expf(logits[l] - mx);
        red2[0] = mx;
        red2[1] = se;
    }
    __syncthreads();
    if (t < 10) {
        float lsm = logits[t] - red2[0] - logf(red2[1]);
        out[g * 10 + t] = lsm;
        out[N_GRAPHS * 10 + g * 10 + t] = expf(lsm);
    }
}

// ---------------- launch ----------------
extern "C" void kernel_launch(void* const* d_in, const int* in_sizes, int n_in,
                              void* d_out, int out_size) {
    const float* x     = (const float*)d_in[0];
    const int*   ei    = (const int*)d_in[1];
    const int*   batch = (const int*)d_in[2];
    const float* W1 = (const float*)d_in[4];  const float* b1 = (const float*)d_in[5];
    const float* W2 = (const float*)d_in[6];  const float* b2 = (const float*)d_in[7];
    const float* W3 = (const float*)d_in[8];  const float* b3 = (const float*)d_in[9];
    const float* W4 = (const float*)d_in[10]; const float* b4 = (const float*)d_in[11];
    const float* W5 = (const float*)d_in[12]; const float* b5 = (const float*)d_in[13];
    const float* W6 = (const float*)d_in[14]; const float* b6 = (const float*)d_in[15];
    const float* Wlin = (const float*)d_in[16];
    const float* blin = (const float*)d_in[17];
    const int* src = ei;
    const int* dst = ei + N_EDGES;
    float* out = (float*)d_out;

    __half *hA, *hB, *Wh;
    float *h6;
    cudaGetSymbolAddress((void**)&hA, g_hA);
    cudaGetSymbolAddress((void**)&hB, g_hB);
    cudaGetSymbolAddress((void**)&h6, g_h6);
    cudaGetSymbolAddress((void**)&Wh, g_Wh);

    const int TB = 256;
    int gN = (N_NODES + TB - 1) / TB;
    int gE = (N_EDGES + TB - 1) / TB;

    // preprocessing (+ converts)
    k_init<<<gN, TB>>>();
    k_tohalf<<<(N_NODES * 32 + TB - 1) / TB, TB>>>(x);
    k_wconv<<<64, 256>>>(W1, 32768, OFF_W1);
    k_wconv<<<128, 256>>>(W2, 65536, OFF_W2);
    k_wconv<<<128, 256>>>(W3, 65536, OFF_W3);
    k_wconv<<<64, 256>>>(W4, 32768, OFF_W4);
    k_wconv<<<32, 256>>>(W5, 16384, OFF_W5);
    k_wconv<<<16, 256>>>(W6, 8192, OFF_W6);
    k_hist<<<gE, TB>>>(dst);
    k_scan1<<<NBLK, 1024>>>();
    k_scan2<<<1, 128>>>();
    k_scan3<<<NBLK, 1024>>>();
    k_fill<<<gE, TB>>>(src, dst);

    int aggBlocks = N_NODES / 8;
    dim3 g256(4, 782), g128(2, 782), g64(1, 782);

    // L1: aggregate-first (128 ch) on half x, then GEMM 128->256 (+bias+relu)
    k_agg<128, false><<<aggBlocks, 256>>>(hA, hB, nullptr, 0, 128, 0);
    k_gemm<<<g256, 256>>>(hB, Wh + OFF_W1, hA, 128, 256, b1, 1);
    // L2: transform-first, split agg
    k_gemm<<<g256, 256>>>(hA, Wh + OFF_W2, hB, 256, 256, nullptr, 0);
    k_agg<128, false><<<aggBlocks, 256>>>(hB, hA, b2, 1, 256, 0);
    k_agg<128, false><<<aggBlocks, 256>>>(hB, hA, b2, 1, 256, 128);
    // L3
    k_gemm<<<g256, 256>>>(hA, Wh + OFF_W3, hB, 256, 256, nullptr, 0);
    k_agg<128, false><<<aggBlocks, 256>>>(hB, hA, b3, 1, 256, 0);
    k_agg<128, false><<<aggBlocks, 256>>>(hB, hA, b3, 1, 256, 128);
    // L4: 256->128
    k_gemm<<<g128, 256>>>(hA, Wh + OFF_W4, hB, 256, 128, nullptr, 0);
    k_agg<128, false><<<aggBlocks, 256>>>(hB, hA, b4, 1, 128, 0);
    // L5: 128->128
    k_gemm<<<g128, 256>>>(hA, Wh + OFF_W5, hB, 128, 128, nullptr, 0);
    k_agg<128, false><<<aggBlocks, 256>>>(hB, hA, b5, 1, 128, 0);
    // L6: 128->64, no relu; agg writes fp32 for pooling
    k_gemm<<<g64, 256>>>(hA, Wh + OFF_W6, hB, 128, 64, nullptr, 0);
    k_agg<64, true><<<aggBlocks, 256>>>(hB, h6, b6, 0, 64, 0);

    // pooling + head
    k_pool<<<(N_NODES * 16 + TB - 1) / TB, TB>>>(h6, batch);
    k_cnt<<<gN, TB>>>(batch);
    k_final<<<N_GRAPHS, 64>>>(Wlin, blin, out);
}